// round 14
// baseline (speedup 1.0000x reference)
#include <cuda_runtime.h>
#include <cuda_fp16.h>
#include <math.h>
#include <stdint.h>

#define NN 512
#define CC 128
#define NPOS (NN*NN)

__device__ __half g_a[(size_t)CC * NPOS];
__device__ __half g_b[(size_t)CC * NPOS];
__device__ __half g_t16[(size_t)CC * NPOS];
__device__ __half g_x16[(size_t)CC * NPOS];   // LN1(pair) in fp16, row-major

// fp16 weight copies (filled by kW once per launch)
__device__ __half g_wp[256*128];
__device__ __half g_wg[256*128];
__device__ __half g_wo[128*128];
__device__ __half g_wgl[128*128];

// ---------------------------------------------------------------------------
// helpers
// ---------------------------------------------------------------------------
__device__ __forceinline__ void mma16(float* d, const uint32_t* a, const uint32_t* b) {
    asm volatile(
        "mma.sync.aligned.m16n8k16.row.col.f32.f16.f16.f32 "
        "{%0,%1,%2,%3}, {%4,%5,%6,%7}, {%8,%9}, {%0,%1,%2,%3};\n"
        : "+f"(d[0]), "+f"(d[1]), "+f"(d[2]), "+f"(d[3])
        : "r"(a[0]), "r"(a[1]), "r"(a[2]), "r"(a[3]), "r"(b[0]), "r"(b[1]));
}
__device__ __forceinline__ void ldsm4(uint32_t* r, uint32_t addr) {
    asm volatile("ldmatrix.sync.aligned.m8n8.x4.shared.b16 {%0,%1,%2,%3}, [%4];"
                 : "=r"(r[0]), "=r"(r[1]), "=r"(r[2]), "=r"(r[3]) : "r"(addr));
}
__device__ __forceinline__ void ldsm4t(uint32_t* r, uint32_t addr) {
    asm volatile("ldmatrix.sync.aligned.m8n8.x4.trans.shared.b16 {%0,%1,%2,%3}, [%4];"
                 : "=r"(r[0]), "=r"(r[1]), "=r"(r[2]), "=r"(r[3]) : "r"(addr));
}
__device__ __forceinline__ float sigm(float x) {
    return __fdividef(1.f, 1.f + __expf(-x));
}
__device__ __forceinline__ uint32_t sptr(const void* p) {
    return (uint32_t)__cvta_generic_to_shared(p);
}
__device__ __forceinline__ void cpa16(uint32_t dst, const void* src) {
    asm volatile("cp.async.cg.shared.global [%0], [%1], 16;" :: "r"(dst), "l"(src));
}

#define HP 136   // half pad for row-major operand tiles
#define CMP 72   // half pad for channel-major tri tile

// ---------------------------------------------------------------------------
// kW: convert weights to fp16 once
// ---------------------------------------------------------------------------
__global__ void __launch_bounds__(256) kW(const float* __restrict__ Wp,
                                          const float* __restrict__ Wg,
                                          const float* __restrict__ Wo,
                                          const float* __restrict__ Wgl)
{
    int idx = blockIdx.x * 256 + threadIdx.x;
    g_wp[idx] = __float2half_rn(Wp[idx]);
    g_wg[idx] = __float2half_rn(Wg[idx]);
    if (idx < 16384) {
        g_wo [idx] = __float2half_rn(Wo [idx]);
        g_wgl[idx] = __float2half_rn(Wgl[idx]);
    }
}

// ---------------------------------------------------------------------------
// Kernel A: LN1 + fp16 MMA vs Wp/Wg + mask*sigmoid + split
// Also exports LN'd x (fp16) to g_x16 for kC.
// ---------------------------------------------------------------------------
#define KA_SMEM ((128*HP + 128*HP + 64*HP)*2 + 128*4 + 16)

__global__ void __launch_bounds__(256, 2) kA(const float* __restrict__ pair,
                                             const float* __restrict__ mask,
                                             const float* __restrict__ w1,
                                             const float* __restrict__ b1)
{
    extern __shared__ char smraw[];
    __half* xh    = (__half*)smraw;               // 128*HP
    __half* wh    = xh + 128*HP;                  // 128*HP (wp | wg chunk)
    __half* stage = wh + 128*HP;                  // 64*HP
    float*  mrow  = (float*)(stage + 64*HP);      // 128

    const int tid = threadIdx.x;
    const int p0  = blockIdx.x * 128;
    const int warp = tid >> 5, lane = tid & 31;
    const uint32_t whb = sptr(wh);

    auto load_w = [&](int o0) {
        #pragma unroll
        for (int it = 0; it < 8; ++it) {
            int idx = it*256 + tid;
            int m = idx >> 10, j = idx & 1023;
            int n = j >> 4, g = j & 15;
            const __half* src = (m ? g_wg : g_wp) + (size_t)(o0+n)*CC + g*8;
            cpa16(whb + (uint32_t)((m*64*HP + n*HP + g*8) * 2), src);
        }
        asm volatile("cp.async.commit_group;");
    };

    load_w(0);

    if (tid < 128) mrow[tid] = mask[p0 + tid];

    {
        float4 wv = *(const float4*)&w1[4*lane];
        float4 bv = *(const float4*)&b1[4*lane];
        #pragma unroll
        for (int rr = 0; rr < 16; ++rr) {
            int r = warp*16 + rr;
            float4 v = *(const float4*)&pair[(size_t)(p0 + r)*CC + 4*lane];
            float s  = v.x+v.y+v.z+v.w;
            float s2 = v.x*v.x+v.y*v.y+v.z*v.z+v.w*v.w;
            #pragma unroll
            for (int o = 16; o; o >>= 1) {
                s  += __shfl_xor_sync(0xffffffffu, s , o);
                s2 += __shfl_xor_sync(0xffffffffu, s2, o);
            }
            float mu = s*(1.f/128.f), var = s2*(1.f/128.f) - mu*mu;
            float rstd = rsqrtf(var + 1e-5f);
            *(__half2*)&xh[r*HP + 4*lane] =
                __floats2half2_rn((v.x-mu)*rstd*wv.x + bv.x, (v.y-mu)*rstd*wv.y + bv.y);
            *(__half2*)&xh[r*HP + 4*lane + 2] =
                __floats2half2_rn((v.z-mu)*rstd*wv.z + bv.z, (v.w-mu)*rstd*wv.w + bv.w);
        }
    }
    __syncthreads();

    // export LN'd x to g_x16 (coalesced: 128 rows x 64 u32)
    #pragma unroll
    for (int it = 0; it < 32; ++it) {
        int idx = it*256 + tid;                   // 0..8191
        int r = idx >> 6, q = idx & 63;
        uint32_t val = *(const uint32_t*)&xh[r*HP + 2*q];
        *(uint32_t*)&g_x16[(size_t)(p0 + r)*CC + 2*q] = val;
    }

    const int wm = warp & 3;
    const int wn = warp >> 2;
    const int gid = lane >> 2, tig = lane & 3;
    const int lrow = lane & 7;
    const int am8  = (lane >> 3) & 1;
    const int am16 = (lane >> 4) & 1;

    const uint32_t aab = sptr(xh) + (uint32_t)(((32*wm + am8*8 + lrow)*HP + am16*8) * 2);
    const uint32_t bab = whb + (uint32_t)(((32*wn + am16*8 + lrow)*HP + am8*8) * 2);

    for (int oc = 0; oc < 4; ++oc) {
        const int o0 = oc * 64;
        asm volatile("cp.async.wait_group 0;");
        __syncthreads();

        float accP[2][4][4] = {}, accG[2][4][4] = {};

        #pragma unroll
        for (int kk = 0; kk < 128; kk += 16) {
            uint32_t a[2][4], bp[2][4], bg[2][4];
            ldsm4(a[0], aab + (uint32_t)(kk*2));
            ldsm4(a[1], aab + (uint32_t)((16*HP + kk)*2));
            ldsm4(bp[0], bab + (uint32_t)(kk*2));
            ldsm4(bp[1], bab + (uint32_t)((16*HP + kk)*2));
            ldsm4(bg[0], bab + (uint32_t)((64*HP + kk)*2));
            ldsm4(bg[1], bab + (uint32_t)((80*HP + kk)*2));
            #pragma unroll
            for (int mt = 0; mt < 2; ++mt)
                #pragma unroll
                for (int nt = 0; nt < 4; ++nt) {
                    mma16(accP[mt][nt], a[mt], &bp[nt>>1][2*(nt&1)]);
                    mma16(accG[mt][nt], a[mt], &bg[nt>>1][2*(nt&1)]);
                }
        }
        __syncthreads();

        if (oc < 3) load_w(o0 + 64);

        #pragma unroll
        for (int mt = 0; mt < 2; ++mt) {
            int rl0 = 32*wm + 16*mt + gid;
            int rl1 = rl0 + 8;
            float m0 = mrow[rl0], m1 = mrow[rl1];
            #pragma unroll
            for (int nt = 0; nt < 4; ++nt) {
                int cl = 32*wn + 8*nt + 2*tig;
                const float* P = accP[mt][nt];
                const float* G = accG[mt][nt];
                stage[cl*HP + rl0]     = __float2half_rn(P[0] * m0 * sigm(G[0]));
                stage[(cl+1)*HP + rl0] = __float2half_rn(P[1] * m0 * sigm(G[1]));
                stage[cl*HP + rl1]     = __float2half_rn(P[2] * m1 * sigm(G[2]));
                stage[(cl+1)*HP + rl1] = __float2half_rn(P[3] * m1 * sigm(G[3]));
            }
        }
        __syncthreads();

        #pragma unroll
        for (int it = 0; it < 16; ++it) {
            int w = it*256 + tid;
            int seg = w >> 6, rw = w & 63;
            int og = o0 + seg;
            uint32_t val = *(const uint32_t*)&stage[seg*HP + 2*rw];
            __half* dst = (og & 1) ? g_b : g_a;
            *(uint32_t*)&dst[(size_t)(og >> 1)*NPOS + p0 + 2*rw] = val;
        }
        __syncthreads();
    }
}

// ---------------------------------------------------------------------------
// Kernel B: per-channel NT fp16 GEMM, 3-stage cp.async pipeline (unchanged)
// ---------------------------------------------------------------------------
#define KBP 40
#define KB_BUF (128*KBP)
#define KB_SMEM (3*2*KB_BUF*2)

__global__ void __launch_bounds__(256, 2) kB()
{
    extern __shared__ __half kbsm[];
    __half* As = kbsm;
    __half* Bs = kbsm + 3*KB_BUF;
    const uint32_t sA = sptr(As);
    const uint32_t sB = sptr(Bs);

    const int c  = blockIdx.z;
    const __half* __restrict__ A = g_a + (size_t)c * NPOS;
    const __half* __restrict__ B = g_b + (size_t)c * NPOS;
    __half* __restrict__ T = g_t16 + (size_t)c * NPOS;
    const int i0 = blockIdx.y * 128;
    const int j0 = blockIdx.x * 128;

    const int tid = threadIdx.x;
    const int warp = tid >> 5, lane = tid & 31;
    const int wm = warp & 1;
    const int wn = warp >> 1;
    const int gid = lane >> 2, tig = lane & 3;
    const int lrow = lane & 7;
    const int am8  = (lane >> 3) & 1;
    const int am16 = (lane >> 4) & 1;

    const uint32_t aoff = (uint32_t)(((64*wm + am8*8 + lrow)*KBP + am16*8) * 2);
    const uint32_t boff = (uint32_t)(((32*wn + am16*8 + lrow)*KBP + am8*8) * 2);
    const uint32_t bufbytes = (uint32_t)(KB_BUF*2);

    float acc[4][4][4] = {};

    auto load_chunk = [&](int buf, int k0) {
        const uint32_t bo = (uint32_t)buf * bufbytes;
        #pragma unroll
        for (int it = 0; it < 2; ++it) {
            int idx = it*256 + tid;
            int row = idx >> 2, g = idx & 3;
            uint32_t doff = (uint32_t)(row*KBP*2 + g*16);
            cpa16(sA + bo + doff, &A[(size_t)(i0+row)*NN + k0 + g*8]);
            cpa16(sB + bo + doff, &B[(size_t)(j0+row)*NN + k0 + g*8]);
        }
        asm volatile("cp.async.commit_group;");
    };

    load_chunk(0, 0);
    load_chunk(1, 32);

    #pragma unroll 1
    for (int kt = 0; kt < 16; ++kt) {
        if (kt < 15) asm volatile("cp.async.wait_group 1;");
        else         asm volatile("cp.async.wait_group 0;");
        __syncthreads();

        if (kt + 2 < 16) load_chunk((kt + 2) % 3, (kt + 2) * 32);

        const uint32_t cb = (uint32_t)(kt % 3) * bufbytes;
        #pragma unroll
        for (int s = 0; s < 2; ++s) {
            const uint32_t ks = (uint32_t)(s * 16 * 2);
            uint32_t a[4][4], bq[2][4];
            #pragma unroll
            for (int mt = 0; mt < 4; ++mt)
                ldsm4(a[mt], sA + cb + aoff + (uint32_t)(16*mt*KBP*2) + ks);
            ldsm4(bq[0], sB + cb + boff + ks);
            ldsm4(bq[1], sB + cb + boff + (uint32_t)(16*KBP*2) + ks);
            #pragma unroll
            for (int mt = 0; mt < 4; ++mt)
                #pragma unroll
                for (int nt = 0; nt < 4; ++nt)
                    mma16(acc[mt][nt], a[mt], &bq[nt>>1][2*(nt&1)]);
        }
    }

    #pragma unroll
    for (int mt = 0; mt < 4; ++mt) {
        int r0 = i0 + 64*wm + 16*mt + gid;
        #pragma unroll
        for (int nt = 0; nt < 4; ++nt) {
            int cbn = j0 + 32*wn + 8*nt + 2*tig;
            *(__half2*)&T[(size_t)r0*NN + cbn]     = __floats2half2_rn(acc[mt][nt][0], acc[mt][nt][1]);
            *(__half2*)&T[(size_t)(r0+8)*NN + cbn] = __floats2half2_rn(acc[mt][nt][2], acc[mt][nt][3]);
        }
    }
}

// ---------------------------------------------------------------------------
// Kernel C: LN2(tri)@Wo^T * sigmoid(x@Wgl^T) + pair, x = g_x16 (precomputed)
// No LN1 recompute: x streams in via cp.async during gather+LN2.
// ---------------------------------------------------------------------------
#define OSP 132  // f32 stage pad
#define KC_SMEM ((256*HP + 128*CMP + 64*HP)*2 + (512+512+128+128)*4 + 16)

__global__ void __launch_bounds__(256, 2) kC(const float* __restrict__ pair,
                                             const float* __restrict__ w2,
                                             const float* __restrict__ b2,
                                             float* __restrict__ out)
{
    extern __shared__ char smraw[];
    __half* wh    = (__half*)smraw;               // 256*HP (Wo | Wgl)
    __half* th_cm = wh + 256*HP;                  // 128*CMP  [channel][pos]
    __half* xh    = th_cm + 128*CMP;              // 64*HP
    float*  rs    = (float*)(xh + 64*HP);         // 8*64
    float*  rq    = rs + 512;                     // 8*64
    float*  w2s   = rq + 512;                     // 128
    float*  b2s   = w2s + 128;                    // 128
    float*  ost   = (float*)wh;                   // 64*OSP f32 stage (reuses wh)

    const int tid = threadIdx.x;
    const int p0  = blockIdx.x * 64;
    const int warp = tid >> 5, lane = tid & 31;
    const uint32_t whb = sptr(wh);
    const uint32_t thb = sptr(th_cm);
    const uint32_t xhb = sptr(xh);

    // group 1: tri copy (channel-major)
    #pragma unroll
    for (int it = 0; it < 4; ++it) {
        int idx = it*256 + tid;
        int cch = idx >> 3, g = idx & 7;
        cpa16(thb + (uint32_t)((cch*CMP + g*8) * 2),
              &g_t16[(size_t)cch*NPOS + p0 + g*8]);
    }
    asm volatile("cp.async.commit_group;");

    // group 2: x copy (row-major, 64 rows x 16 chunks)
    #pragma unroll
    for (int it = 0; it < 4; ++it) {
        int idx = it*256 + tid;                   // 0..1023
        int r = idx >> 4, g = idx & 15;
        cpa16(xhb + (uint32_t)((r*HP + g*8) * 2),
              &g_x16[(size_t)(p0 + r)*CC + g*8]);
    }
    asm volatile("cp.async.commit_group;");

    // group 3: weights (both matrices)
    #pragma unroll
    for (int it = 0; it < 16; ++it) {
        int idx = it*256 + tid;
        int n = idx >> 4, g = idx & 15;
        const __half* src = (n < 128) ? (g_wo + (size_t)n*CC + g*8)
                                      : (g_wgl + (size_t)(n-128)*CC + g*8);
        cpa16(whb + (uint32_t)((n*HP + g*8) * 2), src);
    }
    asm volatile("cp.async.commit_group;");

    if (tid < 128) w2s[tid] = w2[tid];
    else           b2s[tid-128] = b2[tid-128];

    // tri arrived (2 groups still pending)
    asm volatile("cp.async.wait_group 2;");
    __syncthreads();

    // LN2 channel-major
    {
        uint32_t v[16];
        float s0=0.f, s1=0.f, q0=0.f, q1=0.f;
        #pragma unroll
        for (int i = 0; i < 16; ++i) {
            v[i] = *(const uint32_t*)&th_cm[(warp*16 + i)*CMP + 2*lane];
            __half2 h = *(__half2*)&v[i];
            float lo = __low2float(h), hi = __high2float(h);
            s0 += lo; q0 += lo*lo; s1 += hi; q1 += hi*hi;
        }
        *(float2*)&rs[warp*64 + 2*lane] = make_float2(s0, s1);
        *(float2*)&rq[warp*64 + 2*lane] = make_float2(q0, q1);
        __syncthreads();
        float S0=0.f, S1=0.f, Q0=0.f, Q1=0.f;
        #pragma unroll
        for (int w8 = 0; w8 < 8; ++w8) {
            float2 a = *(const float2*)&rs[w8*64 + 2*lane];
            float2 b = *(const float2*)&rq[w8*64 + 2*lane];
            S0 += a.x; S1 += a.y; Q0 += b.x; Q1 += b.y;
        }
        float mu0 = S0*(1.f/128.f), r0 = rsqrtf(Q0*(1.f/128.f) - mu0*mu0 + 1e-5f);
        float mu1 = S1*(1.f/128.f), r1 = rsqrtf(Q1*(1.f/128.f) - mu1*mu1 + 1e-5f);
        #pragma unroll
        for (int i = 0; i < 16; ++i) {
            int cch = warp*16 + i;
            float wv = w2s[cch], bv = b2s[cch];
            __half2 h = *(__half2*)&v[i];
            float lo = (__low2float(h)  - mu0)*r0*wv + bv;
            float hi = (__high2float(h) - mu1)*r1*wv + bv;
            *(__half2*)&th_cm[cch*CMP + 2*lane] = __floats2half2_rn(lo, hi);
        }
    }

    // x + weights arrived
    asm volatile("cp.async.wait_group 0;");
    __syncthreads();

    // MMA
    const int wm = warp & 1;
    const int wn = warp >> 1;
    const int gid = lane >> 2, tig = lane & 3;
    const int lrow = lane & 7;
    const int am8  = (lane >> 3) & 1;
    const int am16 = (lane >> 4) & 1;

    const uint32_t atb = thb + (uint32_t)(((am16*8 + lrow)*CMP + 32*wm + am8*8) * 2);
    const uint32_t axb = xhb + (uint32_t)(((32*wm + am8*8 + lrow)*HP + am16*8) * 2);
    const uint32_t bob = whb + (uint32_t)(((32*wn + am16*8 + lrow)*HP + am8*8) * 2);
    const uint32_t bgb = bob + (uint32_t)(128*HP*2);

    float accO[2][4][4] = {}, accG[2][4][4] = {};

    #pragma unroll
    for (int kk = 0; kk < 128; kk += 16) {
        uint32_t at[2][4], ax[2][4], bo[2][4], bg[2][4];
        ldsm4t(at[0], atb + (uint32_t)(kk*CMP*2));
        ldsm4t(at[1], atb + (uint32_t)(kk*CMP*2 + 16*2));
        ldsm4(ax[0], axb + (uint32_t)(kk*2));
        ldsm4(ax[1], axb + (uint32_t)((16*HP + kk)*2));
        ldsm4(bo[0], bob + (uint32_t)(kk*2));
        ldsm4(bo[1], bob + (uint32_t)((16*HP + kk)*2));
        ldsm4(bg[0], bgb + (uint32_t)(kk*2));
        ldsm4(bg[1], bgb + (uint32_t)((16*HP + kk)*2));
        #pragma unroll
        for (int mt = 0; mt < 2; ++mt)
            #pragma unroll
            for (int nt = 0; nt < 4; ++nt) {
                mma16(accO[mt][nt], at[mt], &bo[nt>>1][2*(nt&1)]);
                mma16(accG[mt][nt], ax[mt], &bg[nt>>1][2*(nt&1)]);
            }
    }
    __syncthreads();   // done reading wh -> reuse as f32 stage

    // stage y = O * sigm(G)
    #pragma unroll
    for (int mt = 0; mt < 2; ++mt) {
        int rl0 = 32*wm + 16*mt + gid;
        #pragma unroll
        for (int nt = 0; nt < 4; ++nt) {
            int col = 32*wn + 8*nt + 2*tig;
            const float* O = accO[mt][nt];
            const float* G = accG[mt][nt];
            *(float2*)&ost[rl0*OSP + col] =
                make_float2(O[0]*sigm(G[0]), O[1]*sigm(G[1]));
            *(float2*)&ost[(rl0+8)*OSP + col] =
                make_float2(O[2]*sigm(G[2]), O[3]*sigm(G[3]));
        }
    }
    __syncthreads();

    // coalesced residual+store pass
    #pragma unroll
    for (int it = 0; it < 8; ++it) {
        int idx = it*256 + tid;
        int r = idx >> 5, q = idx & 31;
        size_t gaddr = (size_t)(p0 + r)*CC + 4*q;
        float4 pr = *(const float4*)&pair[gaddr];
        const float* y = &ost[r*OSP + 4*q];
        float4 ov;
        ov.x = pr.x + y[0];
        ov.y = pr.y + y[1];
        ov.z = pr.z + y[2];
        ov.w = pr.w + y[3];
        *(float4*)&out[gaddr] = ov;
    }
}

// ---------------------------------------------------------------------------
extern "C" void kernel_launch(void* const* d_in, const int* in_sizes, int n_in,
                              void* d_out, int out_size)
{
    const float* pair = (const float*)d_in[0];
    const float* mask = (const float*)d_in[1];
    const float* w1   = (const float*)d_in[2];
    const float* b1   = (const float*)d_in[3];
    const float* Wp   = (const float*)d_in[4];
    const float* Wg   = (const float*)d_in[5];
    const float* w2   = (const float*)d_in[6];
    const float* b2   = (const float*)d_in[7];
    const float* Wo   = (const float*)d_in[8];
    const float* Wgl  = (const float*)d_in[9];
    float* out = (float*)d_out;

    cudaFuncSetAttribute(kA, cudaFuncAttributeMaxDynamicSharedMemorySize, (int)KA_SMEM);
    cudaFuncSetAttribute(kB, cudaFuncAttributeMaxDynamicSharedMemorySize, (int)KB_SMEM);
    cudaFuncSetAttribute(kC, cudaFuncAttributeMaxDynamicSharedMemorySize, (int)KC_SMEM);

    kW<<<128, 256>>>(Wp, Wg, Wo, Wgl);
    kA<<<NPOS/128, 256, KA_SMEM>>>(pair, mask, w1, b1);
    kB<<<dim3(NN/128, NN/128, CC), 256, KB_SMEM>>>();
    kC<<<NPOS/64, 256, KC_SMEM>>>(pair, w2, b2, out);
}

// round 15
// speedup vs baseline: 1.0125x; 1.0125x over previous
#include <cuda_runtime.h>
#include <cuda_fp16.h>
#include <math.h>
#include <stdint.h>

#define NN 512
#define CC 128
#define NPOS (NN*NN)

__device__ __half g_a[(size_t)CC * NPOS];
__device__ __half g_b[(size_t)CC * NPOS];
__device__ __half g_t16[(size_t)CC * NPOS];
__device__ __half g_x16[(size_t)CC * NPOS];   // LN1(pair) in fp16, row-major

// fp16 weight copies (filled by kW once per launch)
__device__ __half g_wp[256*128];
__device__ __half g_wg[256*128];
__device__ __half g_wo[128*128];
__device__ __half g_wgl[128*128];

// ---------------------------------------------------------------------------
// helpers
// ---------------------------------------------------------------------------
__device__ __forceinline__ void mma16(float* d, const uint32_t* a, const uint32_t* b) {
    asm volatile(
        "mma.sync.aligned.m16n8k16.row.col.f32.f16.f16.f32 "
        "{%0,%1,%2,%3}, {%4,%5,%6,%7}, {%8,%9}, {%0,%1,%2,%3};\n"
        : "+f"(d[0]), "+f"(d[1]), "+f"(d[2]), "+f"(d[3])
        : "r"(a[0]), "r"(a[1]), "r"(a[2]), "r"(a[3]), "r"(b[0]), "r"(b[1]));
}
__device__ __forceinline__ void ldsm4(uint32_t* r, uint32_t addr) {
    asm volatile("ldmatrix.sync.aligned.m8n8.x4.shared.b16 {%0,%1,%2,%3}, [%4];"
                 : "=r"(r[0]), "=r"(r[1]), "=r"(r[2]), "=r"(r[3]) : "r"(addr));
}
__device__ __forceinline__ void ldsm4t(uint32_t* r, uint32_t addr) {
    asm volatile("ldmatrix.sync.aligned.m8n8.x4.trans.shared.b16 {%0,%1,%2,%3}, [%4];"
                 : "=r"(r[0]), "=r"(r[1]), "=r"(r[2]), "=r"(r[3]) : "r"(addr));
}
__device__ __forceinline__ float sigm(float x) {
    return __fdividef(1.f, 1.f + __expf(-x));
}
__device__ __forceinline__ uint32_t sptr(const void* p) {
    return (uint32_t)__cvta_generic_to_shared(p);
}
__device__ __forceinline__ void cpa16(uint32_t dst, const void* src) {
    asm volatile("cp.async.cg.shared.global [%0], [%1], 16;" :: "r"(dst), "l"(src));
}

#define HP 136   // half pad for row-major operand tiles
#define CMP 72   // half pad for channel-major tri tile

// ---------------------------------------------------------------------------
// kW: convert weights to fp16 once
// ---------------------------------------------------------------------------
__global__ void __launch_bounds__(256) kW(const float* __restrict__ Wp,
                                          const float* __restrict__ Wg,
                                          const float* __restrict__ Wo,
                                          const float* __restrict__ Wgl)
{
    int idx = blockIdx.x * 256 + threadIdx.x;
    g_wp[idx] = __float2half_rn(Wp[idx]);
    g_wg[idx] = __float2half_rn(Wg[idx]);
    if (idx < 16384) {
        g_wo [idx] = __float2half_rn(Wo [idx]);
        g_wgl[idx] = __float2half_rn(Wgl[idx]);
    }
}

// ---------------------------------------------------------------------------
// Kernel A: LN1 + fp16 MMA vs Wp/Wg + mask*sigmoid + split
// g_x16 export is fused into the LN loop (direct register stores, no extra pass)
// ---------------------------------------------------------------------------
#define KA_SMEM ((128*HP + 128*HP + 64*HP)*2 + 128*4 + 16)

__global__ void __launch_bounds__(256, 2) kA(const float* __restrict__ pair,
                                             const float* __restrict__ mask,
                                             const float* __restrict__ w1,
                                             const float* __restrict__ b1)
{
    extern __shared__ char smraw[];
    __half* xh    = (__half*)smraw;               // 128*HP
    __half* wh    = xh + 128*HP;                  // 128*HP (wp | wg chunk)
    __half* stage = wh + 128*HP;                  // 64*HP
    float*  mrow  = (float*)(stage + 64*HP);      // 128

    const int tid = threadIdx.x;
    const int p0  = blockIdx.x * 128;
    const int warp = tid >> 5, lane = tid & 31;
    const uint32_t whb = sptr(wh);

    auto load_w = [&](int o0) {
        #pragma unroll
        for (int it = 0; it < 8; ++it) {
            int idx = it*256 + tid;
            int m = idx >> 10, j = idx & 1023;
            int n = j >> 4, g = j & 15;
            const __half* src = (m ? g_wg : g_wp) + (size_t)(o0+n)*CC + g*8;
            cpa16(whb + (uint32_t)((m*64*HP + n*HP + g*8) * 2), src);
        }
        asm volatile("cp.async.commit_group;");
    };

    load_w(0);

    if (tid < 128) mrow[tid] = mask[p0 + tid];

    // LN1: 8 warps x 16 rows, write smem AND g_x16 straight from registers
    {
        float4 wv = *(const float4*)&w1[4*lane];
        float4 bv = *(const float4*)&b1[4*lane];
        #pragma unroll
        for (int rr = 0; rr < 16; ++rr) {
            int r = warp*16 + rr;
            float4 v = *(const float4*)&pair[(size_t)(p0 + r)*CC + 4*lane];
            float s  = v.x+v.y+v.z+v.w;
            float s2 = v.x*v.x+v.y*v.y+v.z*v.z+v.w*v.w;
            #pragma unroll
            for (int o = 16; o; o >>= 1) {
                s  += __shfl_xor_sync(0xffffffffu, s , o);
                s2 += __shfl_xor_sync(0xffffffffu, s2, o);
            }
            float mu = s*(1.f/128.f), var = s2*(1.f/128.f) - mu*mu;
            float rstd = rsqrtf(var + 1e-5f);
            __half2 h0 = __floats2half2_rn((v.x-mu)*rstd*wv.x + bv.x, (v.y-mu)*rstd*wv.y + bv.y);
            __half2 h1 = __floats2half2_rn((v.z-mu)*rstd*wv.z + bv.z, (v.w-mu)*rstd*wv.w + bv.w);
            *(__half2*)&xh[r*HP + 4*lane]     = h0;
            *(__half2*)&xh[r*HP + 4*lane + 2] = h1;
            uint2 pkd;
            pkd.x = *(const uint32_t*)&h0;
            pkd.y = *(const uint32_t*)&h1;
            *(uint2*)&g_x16[(size_t)(p0 + r)*CC + 4*lane] = pkd;   // coalesced 8B
        }
    }

    const int wm = warp & 3;
    const int wn = warp >> 2;
    const int gid = lane >> 2, tig = lane & 3;
    const int lrow = lane & 7;
    const int am8  = (lane >> 3) & 1;
    const int am16 = (lane >> 4) & 1;

    const uint32_t aab = sptr(xh) + (uint32_t)(((32*wm + am8*8 + lrow)*HP + am16*8) * 2);
    const uint32_t bab = whb + (uint32_t)(((32*wn + am16*8 + lrow)*HP + am8*8) * 2);

    for (int oc = 0; oc < 4; ++oc) {
        const int o0 = oc * 64;
        asm volatile("cp.async.wait_group 0;");
        __syncthreads();

        float accP[2][4][4] = {}, accG[2][4][4] = {};

        #pragma unroll
        for (int kk = 0; kk < 128; kk += 16) {
            uint32_t a[2][4], bp[2][4], bg[2][4];
            ldsm4(a[0], aab + (uint32_t)(kk*2));
            ldsm4(a[1], aab + (uint32_t)((16*HP + kk)*2));
            ldsm4(bp[0], bab + (uint32_t)(kk*2));
            ldsm4(bp[1], bab + (uint32_t)((16*HP + kk)*2));
            ldsm4(bg[0], bab + (uint32_t)((64*HP + kk)*2));
            ldsm4(bg[1], bab + (uint32_t)((80*HP + kk)*2));
            #pragma unroll
            for (int mt = 0; mt < 2; ++mt)
                #pragma unroll
                for (int nt = 0; nt < 4; ++nt) {
                    mma16(accP[mt][nt], a[mt], &bp[nt>>1][2*(nt&1)]);
                    mma16(accG[mt][nt], a[mt], &bg[nt>>1][2*(nt&1)]);
                }
        }
        __syncthreads();

        if (oc < 3) load_w(o0 + 64);

        #pragma unroll
        for (int mt = 0; mt < 2; ++mt) {
            int rl0 = 32*wm + 16*mt + gid;
            int rl1 = rl0 + 8;
            float m0 = mrow[rl0], m1 = mrow[rl1];
            #pragma unroll
            for (int nt = 0; nt < 4; ++nt) {
                int cl = 32*wn + 8*nt + 2*tig;
                const float* P = accP[mt][nt];
                const float* G = accG[mt][nt];
                stage[cl*HP + rl0]     = __float2half_rn(P[0] * m0 * sigm(G[0]));
                stage[(cl+1)*HP + rl0] = __float2half_rn(P[1] * m0 * sigm(G[1]));
                stage[cl*HP + rl1]     = __float2half_rn(P[2] * m1 * sigm(G[2]));
                stage[(cl+1)*HP + rl1] = __float2half_rn(P[3] * m1 * sigm(G[3]));
            }
        }
        __syncthreads();

        #pragma unroll
        for (int it = 0; it < 16; ++it) {
            int w = it*256 + tid;
            int seg = w >> 6, rw = w & 63;
            int og = o0 + seg;
            uint32_t val = *(const uint32_t*)&stage[seg*HP + 2*rw];
            __half* dst = (og & 1) ? g_b : g_a;
            *(uint32_t*)&dst[(size_t)(og >> 1)*NPOS + p0 + 2*rw] = val;
        }
        __syncthreads();
    }
}

// ---------------------------------------------------------------------------
// Kernel B: per-channel NT fp16 GEMM, 3-stage cp.async pipeline (unchanged)
// ---------------------------------------------------------------------------
#define KBP 40
#define KB_BUF (128*KBP)
#define KB_SMEM (3*2*KB_BUF*2)

__global__ void __launch_bounds__(256, 2) kB()
{
    extern __shared__ __half kbsm[];
    __half* As = kbsm;
    __half* Bs = kbsm + 3*KB_BUF;
    const uint32_t sA = sptr(As);
    const uint32_t sB = sptr(Bs);

    const int c  = blockIdx.z;
    const __half* __restrict__ A = g_a + (size_t)c * NPOS;
    const __half* __restrict__ B = g_b + (size_t)c * NPOS;
    __half* __restrict__ T = g_t16 + (size_t)c * NPOS;
    const int i0 = blockIdx.y * 128;
    const int j0 = blockIdx.x * 128;

    const int tid = threadIdx.x;
    const int warp = tid >> 5, lane = tid & 31;
    const int wm = warp & 1;
    const int wn = warp >> 1;
    const int gid = lane >> 2, tig = lane & 3;
    const int lrow = lane & 7;
    const int am8  = (lane >> 3) & 1;
    const int am16 = (lane >> 4) & 1;

    const uint32_t aoff = (uint32_t)(((64*wm + am8*8 + lrow)*KBP + am16*8) * 2);
    const uint32_t boff = (uint32_t)(((32*wn + am16*8 + lrow)*KBP + am8*8) * 2);
    const uint32_t bufbytes = (uint32_t)(KB_BUF*2);

    float acc[4][4][4] = {};

    auto load_chunk = [&](int buf, int k0) {
        const uint32_t bo = (uint32_t)buf * bufbytes;
        #pragma unroll
        for (int it = 0; it < 2; ++it) {
            int idx = it*256 + tid;
            int row = idx >> 2, g = idx & 3;
            uint32_t doff = (uint32_t)(row*KBP*2 + g*16);
            cpa16(sA + bo + doff, &A[(size_t)(i0+row)*NN + k0 + g*8]);
            cpa16(sB + bo + doff, &B[(size_t)(j0+row)*NN + k0 + g*8]);
        }
        asm volatile("cp.async.commit_group;");
    };

    load_chunk(0, 0);
    load_chunk(1, 32);

    #pragma unroll 1
    for (int kt = 0; kt < 16; ++kt) {
        if (kt < 15) asm volatile("cp.async.wait_group 1;");
        else         asm volatile("cp.async.wait_group 0;");
        __syncthreads();

        if (kt + 2 < 16) load_chunk((kt + 2) % 3, (kt + 2) * 32);

        const uint32_t cb = (uint32_t)(kt % 3) * bufbytes;
        #pragma unroll
        for (int s = 0; s < 2; ++s) {
            const uint32_t ks = (uint32_t)(s * 16 * 2);
            uint32_t a[4][4], bq[2][4];
            #pragma unroll
            for (int mt = 0; mt < 4; ++mt)
                ldsm4(a[mt], sA + cb + aoff + (uint32_t)(16*mt*KBP*2) + ks);
            ldsm4(bq[0], sB + cb + boff + ks);
            ldsm4(bq[1], sB + cb + boff + (uint32_t)(16*KBP*2) + ks);
            #pragma unroll
            for (int mt = 0; mt < 4; ++mt)
                #pragma unroll
                for (int nt = 0; nt < 4; ++nt)
                    mma16(acc[mt][nt], a[mt], &bq[nt>>1][2*(nt&1)]);
        }
    }

    #pragma unroll
    for (int mt = 0; mt < 4; ++mt) {
        int r0 = i0 + 64*wm + 16*mt + gid;
        #pragma unroll
        for (int nt = 0; nt < 4; ++nt) {
            int cbn = j0 + 32*wn + 8*nt + 2*tig;
            *(__half2*)&T[(size_t)r0*NN + cbn]     = __floats2half2_rn(acc[mt][nt][0], acc[mt][nt][1]);
            *(__half2*)&T[(size_t)(r0+8)*NN + cbn] = __floats2half2_rn(acc[mt][nt][2], acc[mt][nt][3]);
        }
    }
}

// ---------------------------------------------------------------------------
// Kernel C: LN2(tri)@Wo^T * sigmoid(x@Wgl^T) + pair, x = g_x16 (unchanged R14)
// ---------------------------------------------------------------------------
#define OSP 132  // f32 stage pad
#define KC_SMEM ((256*HP + 128*CMP + 64*HP)*2 + (512+512+128+128)*4 + 16)

__global__ void __launch_bounds__(256, 2) kC(const float* __restrict__ pair,
                                             const float* __restrict__ w2,
                                             const float* __restrict__ b2,
                                             float* __restrict__ out)
{
    extern __shared__ char smraw[];
    __half* wh    = (__half*)smraw;               // 256*HP (Wo | Wgl)
    __half* th_cm = wh + 256*HP;                  // 128*CMP  [channel][pos]
    __half* xh    = th_cm + 128*CMP;              // 64*HP
    float*  rs    = (float*)(xh + 64*HP);         // 8*64
    float*  rq    = rs + 512;                     // 8*64
    float*  w2s   = rq + 512;                     // 128
    float*  b2s   = w2s + 128;                    // 128
    float*  ost   = (float*)wh;                   // 64*OSP f32 stage (reuses wh)

    const int tid = threadIdx.x;
    const int p0  = blockIdx.x * 64;
    const int warp = tid >> 5, lane = tid & 31;
    const uint32_t whb = sptr(wh);
    const uint32_t thb = sptr(th_cm);
    const uint32_t xhb = sptr(xh);

    // group 1: tri copy (channel-major)
    #pragma unroll
    for (int it = 0; it < 4; ++it) {
        int idx = it*256 + tid;
        int cch = idx >> 3, g = idx & 7;
        cpa16(thb + (uint32_t)((cch*CMP + g*8) * 2),
              &g_t16[(size_t)cch*NPOS + p0 + g*8]);
    }
    asm volatile("cp.async.commit_group;");

    // group 2: x copy (row-major)
    #pragma unroll
    for (int it = 0; it < 4; ++it) {
        int idx = it*256 + tid;
        int r = idx >> 4, g = idx & 15;
        cpa16(xhb + (uint32_t)((r*HP + g*8) * 2),
              &g_x16[(size_t)(p0 + r)*CC + g*8]);
    }
    asm volatile("cp.async.commit_group;");

    // group 3: weights (both matrices)
    #pragma unroll
    for (int it = 0; it < 16; ++it) {
        int idx = it*256 + tid;
        int n = idx >> 4, g = idx & 15;
        const __half* src = (n < 128) ? (g_wo + (size_t)n*CC + g*8)
                                      : (g_wgl + (size_t)(n-128)*CC + g*8);
        cpa16(whb + (uint32_t)((n*HP + g*8) * 2), src);
    }
    asm volatile("cp.async.commit_group;");

    if (tid < 128) w2s[tid] = w2[tid];
    else           b2s[tid-128] = b2[tid-128];

    // tri arrived (2 groups still pending)
    asm volatile("cp.async.wait_group 2;");
    __syncthreads();

    // LN2 channel-major
    {
        uint32_t v[16];
        float s0=0.f, s1=0.f, q0=0.f, q1=0.f;
        #pragma unroll
        for (int i = 0; i < 16; ++i) {
            v[i] = *(const uint32_t*)&th_cm[(warp*16 + i)*CMP + 2*lane];
            __half2 h = *(__half2*)&v[i];
            float lo = __low2float(h), hi = __high2float(h);
            s0 += lo; q0 += lo*lo; s1 += hi; q1 += hi*hi;
        }
        *(float2*)&rs[warp*64 + 2*lane] = make_float2(s0, s1);
        *(float2*)&rq[warp*64 + 2*lane] = make_float2(q0, q1);
        __syncthreads();
        float S0=0.f, S1=0.f, Q0=0.f, Q1=0.f;
        #pragma unroll
        for (int w8 = 0; w8 < 8; ++w8) {
            float2 a = *(const float2*)&rs[w8*64 + 2*lane];
            float2 b = *(const float2*)&rq[w8*64 + 2*lane];
            S0 += a.x; S1 += a.y; Q0 += b.x; Q1 += b.y;
        }
        float mu0 = S0*(1.f/128.f), r0 = rsqrtf(Q0*(1.f/128.f) - mu0*mu0 + 1e-5f);
        float mu1 = S1*(1.f/128.f), r1 = rsqrtf(Q1*(1.f/128.f) - mu1*mu1 + 1e-5f);
        #pragma unroll
        for (int i = 0; i < 16; ++i) {
            int cch = warp*16 + i;
            float wv = w2s[cch], bv = b2s[cch];
            __half2 h = *(__half2*)&v[i];
            float lo = (__low2float(h)  - mu0)*r0*wv + bv;
            float hi = (__high2float(h) - mu1)*r1*wv + bv;
            *(__half2*)&th_cm[cch*CMP + 2*lane] = __floats2half2_rn(lo, hi);
        }
    }

    // x + weights arrived
    asm volatile("cp.async.wait_group 0;");
    __syncthreads();

    // MMA
    const int wm = warp & 1;
    const int wn = warp >> 1;
    const int gid = lane >> 2, tig = lane & 3;
    const int lrow = lane & 7;
    const int am8  = (lane >> 3) & 1;
    const int am16 = (lane >> 4) & 1;

    const uint32_t atb = thb + (uint32_t)(((am16*8 + lrow)*CMP + 32*wm + am8*8) * 2);
    const uint32_t axb = xhb + (uint32_t)(((32*wm + am8*8 + lrow)*HP + am16*8) * 2);
    const uint32_t bob = whb + (uint32_t)(((32*wn + am16*8 + lrow)*HP + am8*8) * 2);
    const uint32_t bgb = bob + (uint32_t)(128*HP*2);

    float accO[2][4][4] = {}, accG[2][4][4] = {};

    #pragma unroll
    for (int kk = 0; kk < 128; kk += 16) {
        uint32_t at[2][4], ax[2][4], bo[2][4], bg[2][4];
        ldsm4t(at[0], atb + (uint32_t)(kk*CMP*2));
        ldsm4t(at[1], atb + (uint32_t)(kk*CMP*2 + 16*2));
        ldsm4(ax[0], axb + (uint32_t)(kk*2));
        ldsm4(ax[1], axb + (uint32_t)((16*HP + kk)*2));
        ldsm4(bo[0], bob + (uint32_t)(kk*2));
        ldsm4(bo[1], bob + (uint32_t)((16*HP + kk)*2));
        ldsm4(bg[0], bgb + (uint32_t)(kk*2));
        ldsm4(bg[1], bgb + (uint32_t)((16*HP + kk)*2));
        #pragma unroll
        for (int mt = 0; mt < 2; ++mt)
            #pragma unroll
            for (int nt = 0; nt < 4; ++nt) {
                mma16(accO[mt][nt], at[mt], &bo[nt>>1][2*(nt&1)]);
                mma16(accG[mt][nt], ax[mt], &bg[nt>>1][2*(nt&1)]);
            }
    }
    __syncthreads();   // done reading wh -> reuse as f32 stage

    // stage y = O * sigm(G)
    #pragma unroll
    for (int mt = 0; mt < 2; ++mt) {
        int rl0 = 32*wm + 16*mt + gid;
        #pragma unroll
        for (int nt = 0; nt < 4; ++nt) {
            int col = 32*wn + 8*nt + 2*tig;
            const float* O = accO[mt][nt];
            const float* G = accG[mt][nt];
            *(float2*)&ost[rl0*OSP + col] =
                make_float2(O[0]*sigm(G[0]), O[1]*sigm(G[1]));
            *(float2*)&ost[(rl0+8)*OSP + col] =
                make_float2(O[2]*sigm(G[2]), O[3]*sigm(G[3]));
        }
    }
    __syncthreads();

    // coalesced residual+store pass
    #pragma unroll
    for (int it = 0; it < 8; ++it) {
        int idx = it*256 + tid;
        int r = idx >> 5, q = idx & 31;
        size_t gaddr = (size_t)(p0 + r)*CC + 4*q;
        float4 pr = *(const float4*)&pair[gaddr];
        const float* y = &ost[r*OSP + 4*q];
        float4 ov;
        ov.x = pr.x + y[0];
        ov.y = pr.y + y[1];
        ov.z = pr.z + y[2];
        ov.w = pr.w + y[3];
        *(float4*)&out[gaddr] = ov;
    }
}

// ---------------------------------------------------------------------------
extern "C" void kernel_launch(void* const* d_in, const int* in_sizes, int n_in,
                              void* d_out, int out_size)
{
    const float* pair = (const float*)d_in[0];
    const float* mask = (const float*)d_in[1];
    const float* w1   = (const float*)d_in[2];
    const float* b1   = (const float*)d_in[3];
    const float* Wp   = (const float*)d_in[4];
    const float* Wg   = (const float*)d_in[5];
    const float* w2   = (const float*)d_in[6];
    const float* b2   = (const float*)d_in[7];
    const float* Wo   = (const float*)d_in[8];
    const float* Wgl  = (const float*)d_in[9];
    float* out = (float*)d_out;

    cudaFuncSetAttribute(kA, cudaFuncAttributeMaxDynamicSharedMemorySize, (int)KA_SMEM);
    cudaFuncSetAttribute(kB, cudaFuncAttributeMaxDynamicSharedMemorySize, (int)KB_SMEM);
    cudaFuncSetAttribute(kC, cudaFuncAttributeMaxDynamicSharedMemorySize, (int)KC_SMEM);

    kW<<<128, 256>>>(Wp, Wg, Wo, Wgl);
    kA<<<NPOS/128, 256, KA_SMEM>>>(pair, mask, w1, b1);
    kB<<<dim3(NN/128, NN/128, CC), 256, KB_SMEM>>>();
    kC<<<NPOS/64, 256, KC_SMEM>>>(pair, w2, b2, out);
}

// round 16
// speedup vs baseline: 1.0617x; 1.0487x over previous
#include <cuda_runtime.h>
#include <cuda_fp16.h>
#include <math.h>
#include <stdint.h>

#define NN 512
#define CC 128
#define NPOS (NN*NN)

__device__ __half g_a[(size_t)CC * NPOS];
__device__ __half g_b[(size_t)CC * NPOS];
__device__ __half g_t16[(size_t)CC * NPOS];
__device__ __half g_x16[(size_t)CC * NPOS];   // LN1(pair) in fp16, row-major

// fp16 weight copies (filled by kW once per launch)
__device__ __half g_wp[256*128];
__device__ __half g_wg[256*128];
__device__ __half g_wo[128*128];
__device__ __half g_wgl[128*128];

// ---------------------------------------------------------------------------
// helpers
// ---------------------------------------------------------------------------
__device__ __forceinline__ void mma16(float* d, const uint32_t* a, const uint32_t* b) {
    asm volatile(
        "mma.sync.aligned.m16n8k16.row.col.f32.f16.f16.f32 "
        "{%0,%1,%2,%3}, {%4,%5,%6,%7}, {%8,%9}, {%0,%1,%2,%3};\n"
        : "+f"(d[0]), "+f"(d[1]), "+f"(d[2]), "+f"(d[3])
        : "r"(a[0]), "r"(a[1]), "r"(a[2]), "r"(a[3]), "r"(b[0]), "r"(b[1]));
}
__device__ __forceinline__ void ldsm4(uint32_t* r, uint32_t addr) {
    asm volatile("ldmatrix.sync.aligned.m8n8.x4.shared.b16 {%0,%1,%2,%3}, [%4];"
                 : "=r"(r[0]), "=r"(r[1]), "=r"(r[2]), "=r"(r[3]) : "r"(addr));
}
__device__ __forceinline__ void ldsm4t(uint32_t* r, uint32_t addr) {
    asm volatile("ldmatrix.sync.aligned.m8n8.x4.trans.shared.b16 {%0,%1,%2,%3}, [%4];"
                 : "=r"(r[0]), "=r"(r[1]), "=r"(r[2]), "=r"(r[3]) : "r"(addr));
}
__device__ __forceinline__ float sigm(float x) {
    return __fdividef(1.f, 1.f + __expf(-x));
}
__device__ __forceinline__ uint32_t sptr(const void* p) {
    return (uint32_t)__cvta_generic_to_shared(p);
}
__device__ __forceinline__ void cpa16(uint32_t dst, const void* src) {
    asm volatile("cp.async.cg.shared.global [%0], [%1], 16;" :: "r"(dst), "l"(src));
}

#define HP 136   // half pad for row-major operand tiles
#define CMP 72   // half pad for channel-major tri tile

// ---------------------------------------------------------------------------
// kW: convert weights to fp16 once
// ---------------------------------------------------------------------------
__global__ void __launch_bounds__(256) kW(const float* __restrict__ Wp,
                                          const float* __restrict__ Wg,
                                          const float* __restrict__ Wo,
                                          const float* __restrict__ Wgl)
{
    int idx = blockIdx.x * 256 + threadIdx.x;
    g_wp[idx] = __float2half_rn(Wp[idx]);
    g_wg[idx] = __float2half_rn(Wg[idx]);
    if (idx < 16384) {
        g_wo [idx] = __float2half_rn(Wo [idx]);
        g_wgl[idx] = __float2half_rn(Wgl[idx]);
    }
}

// ---------------------------------------------------------------------------
// Kernel A: LN1 + fp16 MMA vs Wp/Wg + mask*sigmoid + split
// g_x16 export fused into the LN loop (unchanged from R15)
// ---------------------------------------------------------------------------
#define KA_SMEM ((128*HP + 128*HP + 64*HP)*2 + 128*4 + 16)

__global__ void __launch_bounds__(256, 2) kA(const float* __restrict__ pair,
                                             const float* __restrict__ mask,
                                             const float* __restrict__ w1,
                                             const float* __restrict__ b1)
{
    extern __shared__ char smraw[];
    __half* xh    = (__half*)smraw;               // 128*HP
    __half* wh    = xh + 128*HP;                  // 128*HP (wp | wg chunk)
    __half* stage = wh + 128*HP;                  // 64*HP
    float*  mrow  = (float*)(stage + 64*HP);      // 128

    const int tid = threadIdx.x;
    const int p0  = blockIdx.x * 128;
    const int warp = tid >> 5, lane = tid & 31;
    const uint32_t whb = sptr(wh);

    auto load_w = [&](int o0) {
        #pragma unroll
        for (int it = 0; it < 8; ++it) {
            int idx = it*256 + tid;
            int m = idx >> 10, j = idx & 1023;
            int n = j >> 4, g = j & 15;
            const __half* src = (m ? g_wg : g_wp) + (size_t)(o0+n)*CC + g*8;
            cpa16(whb + (uint32_t)((m*64*HP + n*HP + g*8) * 2), src);
        }
        asm volatile("cp.async.commit_group;");
    };

    load_w(0);

    if (tid < 128) mrow[tid] = mask[p0 + tid];

    {
        float4 wv = *(const float4*)&w1[4*lane];
        float4 bv = *(const float4*)&b1[4*lane];
        #pragma unroll
        for (int rr = 0; rr < 16; ++rr) {
            int r = warp*16 + rr;
            float4 v = *(const float4*)&pair[(size_t)(p0 + r)*CC + 4*lane];
            float s  = v.x+v.y+v.z+v.w;
            float s2 = v.x*v.x+v.y*v.y+v.z*v.z+v.w*v.w;
            #pragma unroll
            for (int o = 16; o; o >>= 1) {
                s  += __shfl_xor_sync(0xffffffffu, s , o);
                s2 += __shfl_xor_sync(0xffffffffu, s2, o);
            }
            float mu = s*(1.f/128.f), var = s2*(1.f/128.f) - mu*mu;
            float rstd = rsqrtf(var + 1e-5f);
            __half2 h0 = __floats2half2_rn((v.x-mu)*rstd*wv.x + bv.x, (v.y-mu)*rstd*wv.y + bv.y);
            __half2 h1 = __floats2half2_rn((v.z-mu)*rstd*wv.z + bv.z, (v.w-mu)*rstd*wv.w + bv.w);
            *(__half2*)&xh[r*HP + 4*lane]     = h0;
            *(__half2*)&xh[r*HP + 4*lane + 2] = h1;
            uint2 pkd;
            pkd.x = *(const uint32_t*)&h0;
            pkd.y = *(const uint32_t*)&h1;
            *(uint2*)&g_x16[(size_t)(p0 + r)*CC + 4*lane] = pkd;
        }
    }

    const int wm = warp & 3;
    const int wn = warp >> 2;
    const int gid = lane >> 2, tig = lane & 3;
    const int lrow = lane & 7;
    const int am8  = (lane >> 3) & 1;
    const int am16 = (lane >> 4) & 1;

    const uint32_t aab = sptr(xh) + (uint32_t)(((32*wm + am8*8 + lrow)*HP + am16*8) * 2);
    const uint32_t bab = whb + (uint32_t)(((32*wn + am16*8 + lrow)*HP + am8*8) * 2);

    for (int oc = 0; oc < 4; ++oc) {
        const int o0 = oc * 64;
        asm volatile("cp.async.wait_group 0;");
        __syncthreads();

        float accP[2][4][4] = {}, accG[2][4][4] = {};

        #pragma unroll
        for (int kk = 0; kk < 128; kk += 16) {
            uint32_t a[2][4], bp[2][4], bg[2][4];
            ldsm4(a[0], aab + (uint32_t)(kk*2));
            ldsm4(a[1], aab + (uint32_t)((16*HP + kk)*2));
            ldsm4(bp[0], bab + (uint32_t)(kk*2));
            ldsm4(bp[1], bab + (uint32_t)((16*HP + kk)*2));
            ldsm4(bg[0], bab + (uint32_t)((64*HP + kk)*2));
            ldsm4(bg[1], bab + (uint32_t)((80*HP + kk)*2));
            #pragma unroll
            for (int mt = 0; mt < 2; ++mt)
                #pragma unroll
                for (int nt = 0; nt < 4; ++nt) {
                    mma16(accP[mt][nt], a[mt], &bp[nt>>1][2*(nt&1)]);
                    mma16(accG[mt][nt], a[mt], &bg[nt>>1][2*(nt&1)]);
                }
        }
        __syncthreads();

        if (oc < 3) load_w(o0 + 64);

        #pragma unroll
        for (int mt = 0; mt < 2; ++mt) {
            int rl0 = 32*wm + 16*mt + gid;
            int rl1 = rl0 + 8;
            float m0 = mrow[rl0], m1 = mrow[rl1];
            #pragma unroll
            for (int nt = 0; nt < 4; ++nt) {
                int cl = 32*wn + 8*nt + 2*tig;
                const float* P = accP[mt][nt];
                const float* G = accG[mt][nt];
                stage[cl*HP + rl0]     = __float2half_rn(P[0] * m0 * sigm(G[0]));
                stage[(cl+1)*HP + rl0] = __float2half_rn(P[1] * m0 * sigm(G[1]));
                stage[cl*HP + rl1]     = __float2half_rn(P[2] * m1 * sigm(G[2]));
                stage[(cl+1)*HP + rl1] = __float2half_rn(P[3] * m1 * sigm(G[3]));
            }
        }
        __syncthreads();

        #pragma unroll
        for (int it = 0; it < 16; ++it) {
            int w = it*256 + tid;
            int seg = w >> 6, rw = w & 63;
            int og = o0 + seg;
            uint32_t val = *(const uint32_t*)&stage[seg*HP + 2*rw];
            __half* dst = (og & 1) ? g_b : g_a;
            *(uint32_t*)&dst[(size_t)(og >> 1)*NPOS + p0 + 2*rw] = val;
        }
        __syncthreads();
    }
}

// ---------------------------------------------------------------------------
// Kernel B: per-channel NT fp16 GEMM.
// NEW: K-chunk 64 (128B gmem rows), 3-stage cp.async, 8 iterations,
//      smem-staged coalesced tri stores.
// ---------------------------------------------------------------------------
#define KBP2 72                              // 64 halves + 8 pad
#define KB_BUF2 (128*KBP2)                   // halves per operand buffer
#define KB_SMEM (3*2*KB_BUF2*2)              // 110592 bytes

__global__ void __launch_bounds__(256, 2) kB()
{
    extern __shared__ __half kbsm[];
    __half* As = kbsm;                       // 3 * KB_BUF2
    __half* Bs = kbsm + 3*KB_BUF2;           // 3 * KB_BUF2
    const uint32_t sA = sptr(As);
    const uint32_t sB = sptr(Bs);

    const int c  = blockIdx.z;
    const __half* __restrict__ A = g_a + (size_t)c * NPOS;
    const __half* __restrict__ B = g_b + (size_t)c * NPOS;
    __half* __restrict__ T = g_t16 + (size_t)c * NPOS;
    const int i0 = blockIdx.y * 128;
    const int j0 = blockIdx.x * 128;

    const int tid = threadIdx.x;
    const int warp = tid >> 5, lane = tid & 31;
    const int wm = warp & 1;
    const int wn = warp >> 1;
    const int gid = lane >> 2, tig = lane & 3;
    const int lrow = lane & 7;
    const int am8  = (lane >> 3) & 1;
    const int am16 = (lane >> 4) & 1;

    const uint32_t aoff = (uint32_t)(((64*wm + am8*8 + lrow)*KBP2 + am16*8) * 2);
    const uint32_t boff = (uint32_t)(((32*wn + am16*8 + lrow)*KBP2 + am8*8) * 2);
    const uint32_t bufbytes = (uint32_t)(KB_BUF2*2);

    float acc[4][4][4] = {};

    // loader: 128 rows x 64 halves (128B/row = 8 x 16B chunks)
    auto load_chunk = [&](int buf, int k0) {
        const uint32_t bo = (uint32_t)buf * bufbytes;
        #pragma unroll
        for (int it = 0; it < 4; ++it) {
            int idx = it*256 + tid;              // 0..1023
            int row = idx >> 3, g = idx & 7;
            uint32_t doff = (uint32_t)(row*KBP2*2 + g*16);
            cpa16(sA + bo + doff, &A[(size_t)(i0+row)*NN + k0 + g*8]);
            cpa16(sB + bo + doff, &B[(size_t)(j0+row)*NN + k0 + g*8]);
        }
        asm volatile("cp.async.commit_group;");
    };

    load_chunk(0, 0);
    load_chunk(1, 64);

    #pragma unroll 1
    for (int kt = 0; kt < 8; ++kt) {
        if (kt < 7) asm volatile("cp.async.wait_group 1;");
        else        asm volatile("cp.async.wait_group 0;");
        __syncthreads();

        if (kt + 2 < 8) load_chunk((kt + 2) % 3, (kt + 2) * 64);

        const uint32_t cb = (uint32_t)(kt % 3) * bufbytes;
        #pragma unroll
        for (int s = 0; s < 4; ++s) {
            const uint32_t ks = (uint32_t)(s * 16 * 2);
            uint32_t a[4][4], bq[2][4];
            #pragma unroll
            for (int mt = 0; mt < 4; ++mt)
                ldsm4(a[mt], sA + cb + aoff + (uint32_t)(16*mt*KBP2*2) + ks);
            ldsm4(bq[0], sB + cb + boff + ks);
            ldsm4(bq[1], sB + cb + boff + (uint32_t)(16*KBP2*2) + ks);
            #pragma unroll
            for (int mt = 0; mt < 4; ++mt)
                #pragma unroll
                for (int nt = 0; nt < 4; ++nt)
                    mma16(acc[mt][nt], a[mt], &bq[nt>>1][2*(nt&1)]);
        }
    }
    __syncthreads();    // buffers dead -> reuse As region as stage

    // stage fp16 tri tile (pad HP, conflict-free half2 writes)
    __half* stg = As;   // 128*HP halves = 34816 B
    #pragma unroll
    for (int mt = 0; mt < 4; ++mt) {
        int r0 = 64*wm + 16*mt + gid;
        #pragma unroll
        for (int nt = 0; nt < 4; ++nt) {
            int cbn = 32*wn + 8*nt + 2*tig;
            *(__half2*)&stg[r0*HP + cbn]     = __floats2half2_rn(acc[mt][nt][0], acc[mt][nt][1]);
            *(__half2*)&stg[(r0+8)*HP + cbn] = __floats2half2_rn(acc[mt][nt][2], acc[mt][nt][3]);
        }
    }
    __syncthreads();

    // coalesced copy-out: 128 rows x 256B contiguous (uint4)
    #pragma unroll
    for (int it = 0; it < 8; ++it) {
        int idx = it*256 + tid;              // 0..2047
        int r = idx >> 4, q = idx & 15;
        uint4 v = *(const uint4*)&stg[r*HP + q*8];
        *(uint4*)&T[(size_t)(i0+r)*NN + j0 + q*8] = v;
    }
}

// ---------------------------------------------------------------------------
// Kernel C: LN2(tri)@Wo^T * sigmoid(x@Wgl^T) + pair  (unchanged from R15)
// ---------------------------------------------------------------------------
#define OSP 132  // f32 stage pad
#define KC_SMEM ((256*HP + 128*CMP + 64*HP)*2 + (512+512+128+128)*4 + 16)

__global__ void __launch_bounds__(256, 2) kC(const float* __restrict__ pair,
                                             const float* __restrict__ w2,
                                             const float* __restrict__ b2,
                                             float* __restrict__ out)
{
    extern __shared__ char smraw[];
    __half* wh    = (__half*)smraw;               // 256*HP (Wo | Wgl)
    __half* th_cm = wh + 256*HP;                  // 128*CMP  [channel][pos]
    __half* xh    = th_cm + 128*CMP;              // 64*HP
    float*  rs    = (float*)(xh + 64*HP);         // 8*64
    float*  rq    = rs + 512;                     // 8*64
    float*  w2s   = rq + 512;                     // 128
    float*  b2s   = w2s + 128;                    // 128
    float*  ost   = (float*)wh;                   // 64*OSP f32 stage (reuses wh)

    const int tid = threadIdx.x;
    const int p0  = blockIdx.x * 64;
    const int warp = tid >> 5, lane = tid & 31;
    const uint32_t whb = sptr(wh);
    const uint32_t thb = sptr(th_cm);
    const uint32_t xhb = sptr(xh);

    // group 1: tri copy (channel-major)
    #pragma unroll
    for (int it = 0; it < 4; ++it) {
        int idx = it*256 + tid;
        int cch = idx >> 3, g = idx & 7;
        cpa16(thb + (uint32_t)((cch*CMP + g*8) * 2),
              &g_t16[(size_t)cch*NPOS + p0 + g*8]);
    }
    asm volatile("cp.async.commit_group;");

    // group 2: x copy (row-major)
    #pragma unroll
    for (int it = 0; it < 4; ++it) {
        int idx = it*256 + tid;
        int r = idx >> 4, g = idx & 15;
        cpa16(xhb + (uint32_t)((r*HP + g*8) * 2),
              &g_x16[(size_t)(p0 + r)*CC + g*8]);
    }
    asm volatile("cp.async.commit_group;");

    // group 3: weights (both matrices)
    #pragma unroll
    for (int it = 0; it < 16; ++it) {
        int idx = it*256 + tid;
        int n = idx >> 4, g = idx & 15;
        const __half* src = (n < 128) ? (g_wo + (size_t)n*CC + g*8)
                                      : (g_wgl + (size_t)(n-128)*CC + g*8);
        cpa16(whb + (uint32_t)((n*HP + g*8) * 2), src);
    }
    asm volatile("cp.async.commit_group;");

    if (tid < 128) w2s[tid] = w2[tid];
    else           b2s[tid-128] = b2[tid-128];

    asm volatile("cp.async.wait_group 2;");
    __syncthreads();

    // LN2 channel-major
    {
        uint32_t v[16];
        float s0=0.f, s1=0.f, q0=0.f, q1=0.f;
        #pragma unroll
        for (int i = 0; i < 16; ++i) {
            v[i] = *(const uint32_t*)&th_cm[(warp*16 + i)*CMP + 2*lane];
            __half2 h = *(__half2*)&v[i];
            float lo = __low2float(h), hi = __high2float(h);
            s0 += lo; q0 += lo*lo; s1 += hi; q1 += hi*hi;
        }
        *(float2*)&rs[warp*64 + 2*lane] = make_float2(s0, s1);
        *(float2*)&rq[warp*64 + 2*lane] = make_float2(q0, q1);
        __syncthreads();
        float S0=0.f, S1=0.f, Q0=0.f, Q1=0.f;
        #pragma unroll
        for (int w8 = 0; w8 < 8; ++w8) {
            float2 a = *(const float2*)&rs[w8*64 + 2*lane];
            float2 b = *(const float2*)&rq[w8*64 + 2*lane];
            S0 += a.x; S1 += a.y; Q0 += b.x; Q1 += b.y;
        }
        float mu0 = S0*(1.f/128.f), r0 = rsqrtf(Q0*(1.f/128.f) - mu0*mu0 + 1e-5f);
        float mu1 = S1*(1.f/128.f), r1 = rsqrtf(Q1*(1.f/128.f) - mu1*mu1 + 1e-5f);
        #pragma unroll
        for (int i = 0; i < 16; ++i) {
            int cch = warp*16 + i;
            float wv = w2s[cch], bv = b2s[cch];
            __half2 h = *(__half2*)&v[i];
            float lo = (__low2float(h)  - mu0)*r0*wv + bv;
            float hi = (__high2float(h) - mu1)*r1*wv + bv;
            *(__half2*)&th_cm[cch*CMP + 2*lane] = __floats2half2_rn(lo, hi);
        }
    }

    asm volatile("cp.async.wait_group 0;");
    __syncthreads();

    const int wm = warp & 1;
    const int wn = warp >> 1;
    const int gid = lane >> 2, tig = lane & 3;
    const int lrow = lane & 7;
    const int am8  = (lane >> 3) & 1;
    const int am16 = (lane >> 4) & 1;

    const uint32_t atb = thb + (uint32_t)(((am16*8 + lrow)*CMP + 32*wm + am8*8) * 2);
    const uint32_t axb = xhb + (uint32_t)(((32*wm + am8*8 + lrow)*HP + am16*8) * 2);
    const uint32_t bob = whb + (uint32_t)(((32*wn + am16*8 + lrow)*HP + am8*8) * 2);
    const uint32_t bgb = bob + (uint32_t)(128*HP*2);

    float accO[2][4][4] = {}, accG[2][4][4] = {};

    #pragma unroll
    for (int kk = 0; kk < 128; kk += 16) {
        uint32_t at[2][4], ax[2][4], bo[2][4], bg[2][4];
        ldsm4t(at[0], atb + (uint32_t)(kk*CMP*2));
        ldsm4t(at[1], atb + (uint32_t)(kk*CMP*2 + 16*2));
        ldsm4(ax[0], axb + (uint32_t)(kk*2));
        ldsm4(ax[1], axb + (uint32_t)((16*HP + kk)*2));
        ldsm4(bo[0], bob + (uint32_t)(kk*2));
        ldsm4(bo[1], bob + (uint32_t)((16*HP + kk)*2));
        ldsm4(bg[0], bgb + (uint32_t)(kk*2));
        ldsm4(bg[1], bgb + (uint32_t)((16*HP + kk)*2));
        #pragma unroll
        for (int mt = 0; mt < 2; ++mt)
            #pragma unroll
            for (int nt = 0; nt < 4; ++nt) {
                mma16(accO[mt][nt], at[mt], &bo[nt>>1][2*(nt&1)]);
                mma16(accG[mt][nt], ax[mt], &bg[nt>>1][2*(nt&1)]);
            }
    }
    __syncthreads();

    // stage y = O * sigm(G)
    #pragma unroll
    for (int mt = 0; mt < 2; ++mt) {
        int rl0 = 32*wm + 16*mt + gid;
        #pragma unroll
        for (int nt = 0; nt < 4; ++nt) {
            int col = 32*wn + 8*nt + 2*tig;
            const float* O = accO[mt][nt];
            const float* G = accG[mt][nt];
            *(float2*)&ost[rl0*OSP + col] =
                make_float2(O[0]*sigm(G[0]), O[1]*sigm(G[1]));
            *(float2*)&ost[(rl0+8)*OSP + col] =
                make_float2(O[2]*sigm(G[2]), O[3]*sigm(G[3]));
        }
    }
    __syncthreads();

    // coalesced residual+store pass
    #pragma unroll
    for (int it = 0; it < 8; ++it) {
        int idx = it*256 + tid;
        int r = idx >> 5, q = idx & 31;
        size_t gaddr = (size_t)(p0 + r)*CC + 4*q;
        float4 pr = *(const float4*)&pair[gaddr];
        const float* y = &ost[r*OSP + 4*q];
        float4 ov;
        ov.x = pr.x + y[0];
        ov.y = pr.y + y[1];
        ov.z = pr.z + y[2];
        ov.w = pr.w + y[3];
        *(float4*)&out[gaddr] = ov;
    }
}

// ---------------------------------------------------------------------------
extern "C" void kernel_launch(void* const* d_in, const int* in_sizes, int n_in,
                              void* d_out, int out_size)
{
    const float* pair = (const float*)d_in[0];
    const float* mask = (const float*)d_in[1];
    const float* w1   = (const float*)d_in[2];
    const float* b1   = (const float*)d_in[3];
    const float* Wp   = (const float*)d_in[4];
    const float* Wg   = (const float*)d_in[5];
    const float* w2   = (const float*)d_in[6];
    const float* b2   = (const float*)d_in[7];
    const float* Wo   = (const float*)d_in[8];
    const float* Wgl  = (const float*)d_in[9];
    float* out = (float*)d_out;

    cudaFuncSetAttribute(kA, cudaFuncAttributeMaxDynamicSharedMemorySize, (int)KA_SMEM);
    cudaFuncSetAttribute(kB, cudaFuncAttributeMaxDynamicSharedMemorySize, (int)KB_SMEM);
    cudaFuncSetAttribute(kC, cudaFuncAttributeMaxDynamicSharedMemorySize, (int)KC_SMEM);

    kW<<<128, 256>>>(Wp, Wg, Wo, Wgl);
    kA<<<NPOS/128, 256, KA_SMEM>>>(pair, mask, w1, b1);
    kB<<<dim3(NN/128, NN/128, CC), 256, KB_SMEM>>>();
    kC<<<NPOS/64, 256, KC_SMEM>>>(pair, w2, b2, out);
}